// round 4
// baseline (speedup 1.0000x reference)
#include <cuda_runtime.h>

#define BATCH   4096
#define IN_W    1024
#define DEPTH   8
#define BLOCKS  64
#define NACT    8
#define GROW    512
#define TOTAL   5120
#define OUT_W   512
#define BCOL    4          // batch cols per CTA
#define THREADS 128        // 64 butterfly blocks x 2 col-pairs

typedef unsigned long long ull;

// Pre-packed rotation constants: g_cs[(m*64 + L*8 + q)*64 + blk] = ((c,c),(s,s))
__device__ ulonglong2 g_cs[DEPTH * 64 * BLOCKS];

__device__ __forceinline__ ull pk2(float x, float y) {
    ull r; asm("mov.b64 %0, {%1, %2};" : "=l"(r) : "f"(x), "f"(y)); return r;
}
__device__ __forceinline__ void upk2(ull v, float& x, float& y) {
    asm("mov.b64 {%0, %1}, %2;" : "=f"(x), "=f"(y) : "l"(v));
}
// Packed f32x2 FMA/MUL — Blackwell FFMA2 path (PTX-only)
__device__ __forceinline__ ull fma2(ull a, ull b, ull c) {
    ull d; asm("fma.rn.f32x2 %0, %1, %2, %3;" : "=l"(d) : "l"(a), "l"(b), "l"(c)); return d;
}
__device__ __forceinline__ ull mul2(ull a, ull b) {
    ull d; asm("mul.rn.f32x2 %0, %1, %2;" : "=l"(d) : "l"(a), "l"(b)); return d;
}
__device__ __forceinline__ float sqrt_ap(float x) {
    float r; asm("sqrt.approx.f32 %0, %1;" : "=f"(r) : "f"(x)); return r;
}
__device__ __forceinline__ float actf(float p) {
    return 0.5f * (p + sqrt_ap(fmaf(p, p, 1.0f)));
}

// ---------------------------------------------------------------------------
// One-time: pack trig table. angles: [DEPTH][8][512], 512 = blk*8 + q
// ---------------------------------------------------------------------------
__global__ void trig_kernel(const float* __restrict__ angles) {
    int i = blockIdx.x * blockDim.x + threadIdx.x;
    if (i >= DEPTH * 8 * 512) return;
    int Lm  = i / 512;                 // m*8 + L
    int r   = i % 512;
    int blk = r / 8, q = r % 8;
    float sn, cs;
    sincosf(angles[i], &sn, &cs);
    g_cs[(Lm * 8 + q) * 64 + blk] = make_ulonglong2(pk2(cs, cs), pk2(sn, sn));
}

// ---------------------------------------------------------------------------
// Fused network: one CTA owns BCOL=4 batch columns; full state in smem.
// Thread = (butterfly block blk, col-pair cp). All 8 modules, no global state.
// ---------------------------------------------------------------------------
__global__ __launch_bounds__(THREADS)
void fused_kernel(const float* __restrict__ input,
                  const float* __restrict__ scales,
                  const float* __restrict__ biases,   // [DEPTH][512]
                  const int*   __restrict__ indices,  // [DEPTH][1024]
                  float* __restrict__ out)            // (512, 4096)
{
    extern __shared__ float sd[];                     // [TOTAL][BCOL]
    const int tid = threadIdx.x;
    const int blk = tid >> 1;
    const int cp  = tid & 1;
    const int c0  = blockIdx.x * BCOL;

    // Stage scaled input rows 0..1023 for our 4 cols
    #pragma unroll
    for (int i = 0; i < 16; i++) {
        int e   = tid + THREADS * i;                  // 0..2047 (row, colpair)
        int row = e >> 1, cc = (e & 1) * 2;
        float2 vv = *(const float2*)(input + (size_t)row * BATCH + c0 + cc);
        float s = scales[row];
        vv.x *= s; vv.y *= s;
        *(float2*)(sd + row * BCOL + cc) = vv;
    }
    __syncthreads();

    const ull SGN = 0x8000000080000000ULL;

    #pragma unroll 1
    for (int m = 0; m < DEPTH; m++) {
        const int* idxm = indices + m * 1024 + blk * 16;
        const ulonglong2* tb = g_cs + (size_t)m * 64 * 64 + blk;  // +(L*8+q)*64

        // Gather 16 rows from smem (addresses kept for scatter)
        int sa[16];
        ull v[16];
        #pragma unroll
        for (int j = 0; j < 16; j++) {
            sa[j] = idxm[j] * BCOL + cp * 2;
            v[j]  = *(const ull*)(sd + sa[j]);
        }

        // 4 IN rotation layers (strides 1,2,4,8), all in registers
        #pragma unroll
        for (int k = 0; k < 4; k++) {
            const int st = 1 << k;
            #pragma unroll
            for (int g = 0; g < 16; g += 2 * st) {
                #pragma unroll
                for (int j = 0; j < st; j++) {
                    const int lo = g + j, hi = lo + st;
                    ulonglong2 t = tb[(k * 8 + (g >> 1) + j) * 64];  // LDG.128, L1-hot
                    ull ns = t.y ^ SGN;
                    ull xl = v[lo], xh = v[hi];
                    v[lo] = fma2(t.x, xl, mul2(t.y, xh));
                    v[hi] = fma2(ns,  xl, mul2(t.x, xh));
                }
            }
        }

        // Activation rows 0..7 (+ write: smem act region, or d_out for last)
        const float* bb = biases + m * GROW + blk * NACT;
        const bool last = (m == DEPTH - 1);
        #pragma unroll
        for (int u = 0; u < NACT; u++) {
            float x0, x1; upk2(v[u], x0, x1);
            float b = bb[u];
            x0 = actf(x0 + b); x1 = actf(x1 + b);
            v[u] = pk2(x0, x1);
            if (!last) {
                *(ull*)(sd + (IN_W + GROW * m + blk * NACT + u) * BCOL + cp * 2) = v[u];
            } else {
                float2 o2 = make_float2(x0, x1);
                *(float2*)(out + (size_t)(blk * NACT + u) * BATCH + c0 + cp * 2) = o2;
            }
        }

        if (!last) {
            // 4 OUT rotation layers (trig layers 4..7, strides 1,2,4,8)
            #pragma unroll
            for (int k = 0; k < 4; k++) {
                const int st = 1 << k;
                #pragma unroll
                for (int g = 0; g < 16; g += 2 * st) {
                    #pragma unroll
                    for (int j = 0; j < st; j++) {
                        const int lo = g + j, hi = lo + st;
                        ulonglong2 t = tb[((4 + k) * 8 + (g >> 1) + j) * 64];
                        ull ns = t.y ^ SGN;
                        ull xl = v[lo], xh = v[hi];
                        v[lo] = fma2(t.x, xl, mul2(t.y, xh));
                        v[hi] = fma2(ns,  xl, mul2(t.x, xh));
                    }
                }
            }
            // Scatter back to smem
            #pragma unroll
            for (int j = 0; j < 16; j++)
                *(ull*)(sd + sa[j]) = v[j];
        }
        __syncthreads();
    }
}

// ---------------------------------------------------------------------------
extern "C" void kernel_launch(void* const* d_in, const int* in_sizes, int n_in,
                              void* d_out, int out_size) {
    const float* input   = (const float*)d_in[0];   // (1024, 4096)
    const float* scales  = (const float*)d_in[1];   // (1024,)
    const float* angles  = (const float*)d_in[2];   // (8, 8, 512)
    const float* biases  = (const float*)d_in[3];   // (8, 512)
    const int*   indices = (const int*)d_in[4];     // (8, 1024)
    float* out = (float*)d_out;                     // (512, 4096)

    const int smem = TOTAL * BCOL * sizeof(float);  // 80 KB
    cudaFuncSetAttribute(fused_kernel,
                         cudaFuncAttributeMaxDynamicSharedMemorySize, smem);

    const int nt = DEPTH * 8 * 512;
    trig_kernel<<<(nt + 255) / 256, 256>>>(angles);

    fused_kernel<<<BATCH / BCOL, THREADS, smem>>>(input, scales, biases,
                                                  indices, out);
}

// round 6
// speedup vs baseline: 1.4610x; 1.4610x over previous
#include <cuda_runtime.h>

#define BATCH   4096
#define IN_W    1024
#define DEPTH   8
#define BLOCKS  64
#define NACT    8
#define GROW    512
#define TOTAL   5120
#define OUT_W   512

// 84 MB scratch state (static __device__ global: allowed, no runtime alloc)
__device__ float g_data[(size_t)TOTAL * BATCH];

typedef unsigned long long ull;

// Pre-packed rotation constants: g_cs[(m*64+blk)*64 + L*8 + a] = ((c,c),(s,s))
__device__ ulonglong2 g_cs[DEPTH * BLOCKS * 64];

__device__ __forceinline__ ull pk2(float x, float y) {
    ull r; asm("mov.b64 %0, {%1, %2};" : "=l"(r) : "f"(x), "f"(y)); return r;
}
__device__ __forceinline__ void upk2(ull v, float& x, float& y) {
    asm("mov.b64 {%0, %1}, %2;" : "=f"(x), "=f"(y) : "l"(v));
}
// Packed f32x2 FMA/MUL — Blackwell FFMA2 path (PTX-only)
__device__ __forceinline__ ull fma2(ull a, ull b, ull c) {
    ull d; asm("fma.rn.f32x2 %0, %1, %2, %3;" : "=l"(d) : "l"(a), "l"(b), "l"(c)); return d;
}
__device__ __forceinline__ ull mul2(ull a, ull b) {
    ull d; asm("mul.rn.f32x2 %0, %1, %2;" : "=l"(d) : "l"(a), "l"(b)); return d;
}
__device__ __forceinline__ float sqrt_ap(float x) {
    float r; asm("sqrt.approx.f32 %0, %1;" : "=f"(r) : "f"(x)); return r;
}
__device__ __forceinline__ float actf(float p) {
    return 0.5f * (p + sqrt_ap(fmaf(p, p, 1.0f)));
}
// evict_last access policy (createpolicy + cache_hint works at any width)
__device__ __forceinline__ ull mk_policy() {
    ull pol;
    asm("createpolicy.fractional.L2::evict_last.b64 %0, 1.0;" : "=l"(pol));
    return pol;
}
__device__ __forceinline__ ull ldg_el(const float* p, ull pol) {
    ull v;
    asm("ld.global.L2::cache_hint.b64 %0, [%1], %2;"
        : "=l"(v) : "l"(p), "l"(pol));
    return v;
}
__device__ __forceinline__ void stg_el(float* p, ull v, ull pol) {
    asm volatile("st.global.L2::cache_hint.b64 [%0], %1, %2;"
                 :: "l"(p), "l"(v), "l"(pol));
}
// d_out: streaming store (read-never)
__device__ __forceinline__ void stg_cs(float* p, ull v) {
    asm volatile("st.global.cs.b64 [%0], %1;" :: "l"(p), "l"(v));
}

// ---------------------------------------------------------------------------
// One-time: pack trig table. angles: [DEPTH][8][512], 512 = blk*8 + a
// ---------------------------------------------------------------------------
__global__ void trig_kernel(const float* __restrict__ angles) {
    int i = blockIdx.x * blockDim.x + threadIdx.x;
    if (i >= DEPTH * 8 * 512) return;
    int m = i / 4096, r = i % 4096;
    int L = r / 512,  q = r % 512;
    int blk = q / 8,  a = q % 8;
    float sn, cs;
    sincosf(angles[i], &sn, &cs);
    g_cs[(m * BLOCKS + blk) * 64 + L * 8 + a] =
        make_ulonglong2(pk2(cs, cs), pk2(sn, sn));
}

// ---------------------------------------------------------------------------
// One butterfly module. CUDA block = (butterfly blk) x (256 batch cols).
// Thread owns 2 batch columns of all 16 rows as f32x2; transform in registers.
// MODE: 0 = middle, 1 = first (gather from input*scales), 2 = last (act->out)
// ---------------------------------------------------------------------------
template<int MODE>
__global__ __launch_bounds__(128, 6)
void module_kernel(const float* __restrict__ biases,  // [512] this module
                   const int*   __restrict__ idx,     // [1024] this module
                   int mod,
                   const float* __restrict__ input,   // (1024,4096) for FIRST
                   const float* __restrict__ scales,  // (1024,)     for FIRST
                   float* __restrict__ out_ext)       // d_out for LAST
{
    const int blk = blockIdx.y;
    const int tid = threadIdx.x;

    __shared__ int   s_idx[16];
    __shared__ ull   s_scl[16];
    __shared__ float s_bias[NACT];
    __shared__ __align__(16) ulonglong2 s_cs[64];

    if (tid < 16) {
        int row = idx[blk * 16 + tid];
        s_idx[tid] = row;
        if (MODE == 1) { float s = scales[row]; s_scl[tid] = pk2(s, s); }
    }
    if (tid < 8)  s_bias[tid] = biases[blk * 8 + tid];
    if (tid < 64) s_cs[tid] = g_cs[(mod * BLOCKS + blk) * 64 + tid];
    __syncthreads();

    const int b = (blockIdx.x * 128 + tid) * 2;   // first of 2 batch cols
    const ull SGN = 0x8000000080000000ULL;
    const ull pol = mk_policy();

    // Gather 16 rows (16 independent LDG.64 -> MLP=16)
    ull v[16];
    #pragma unroll
    for (int j = 0; j < 16; j++) {
        if (MODE == 1)
            v[j] = *(const ull*)(input + (size_t)s_idx[j] * BATCH + b);
        else
            v[j] = ldg_el(g_data + (size_t)s_idx[j] * BATCH + b, pol);
    }
    if (MODE == 1) {
        #pragma unroll
        for (int j = 0; j < 16; j++) v[j] = mul2(v[j], s_scl[j]);
    }

    // 4 IN rotation layers (strides 1,2,4,8), all in registers
    #pragma unroll
    for (int k = 0; k < 4; k++) {
        const int st = 1 << k;
        #pragma unroll
        for (int g = 0; g < 16; g += 2 * st) {
            #pragma unroll
            for (int j = 0; j < st; j++) {
                const int lo = g + j, hi = lo + st;
                const ulonglong2 cs = s_cs[k * 8 + (g >> 1) + j];  // LDS.128
                const ull ns = cs.y ^ SGN;                         // -s on ALU
                ull xl = v[lo], xh = v[hi];
                v[lo] = fma2(cs.x, xl, mul2(cs.y, xh));
                v[hi] = fma2(ns,   xl, mul2(cs.x, xh));
            }
        }
    }

    // Activation on rows 0..7; write act rows (d_out for last module)
    #pragma unroll
    for (int u = 0; u < NACT; u++) {
        const float bb = s_bias[u];
        float x0, x1;
        upk2(v[u], x0, x1);
        x0 = actf(x0 + bb); x1 = actf(x1 + bb);
        v[u] = pk2(x0, x1);
        if (MODE == 2)
            stg_cs(out_ext + (size_t)(blk * NACT + u) * BATCH + b, v[u]);
        else
            stg_el(g_data + (size_t)(IN_W + GROW * mod + blk * NACT + u) * BATCH + b,
                   v[u], pol);
    }

    if (MODE != 2) {
        // 4 OUT rotation layers (trig layers 4..7, strides 1,2,4,8)
        #pragma unroll
        for (int k = 0; k < 4; k++) {
            const int st = 1 << k;
            #pragma unroll
            for (int g = 0; g < 16; g += 2 * st) {
                #pragma unroll
                for (int j = 0; j < st; j++) {
                    const int lo = g + j, hi = lo + st;
                    const ulonglong2 cs = s_cs[(4 + k) * 8 + (g >> 1) + j];
                    const ull ns = cs.y ^ SGN;
                    ull xl = v[lo], xh = v[hi];
                    v[lo] = fma2(cs.x, xl, mul2(cs.y, xh));
                    v[hi] = fma2(ns,   xl, mul2(cs.x, xh));
                }
            }
        }
        // Scatter back (16 independent STG.64, pinned in L2)
        #pragma unroll
        for (int j = 0; j < 16; j++)
            stg_el(g_data + (size_t)s_idx[j] * BATCH + b, v[j], pol);
    }
}

// ---------------------------------------------------------------------------
extern "C" void kernel_launch(void* const* d_in, const int* in_sizes, int n_in,
                              void* d_out, int out_size) {
    const float* input   = (const float*)d_in[0];   // (1024, 4096)
    const float* scales  = (const float*)d_in[1];   // (1024,)
    const float* angles  = (const float*)d_in[2];   // (8, 8, 512)
    const float* biases  = (const float*)d_in[3];   // (8, 512)
    const int*   indices = (const int*)d_in[4];     // (8, 1024)
    float* out = (float*)d_out;                     // (512, 4096)

    const int nt = DEPTH * 8 * 512;
    trig_kernel<<<(nt + 255) / 256, 256>>>(angles);

    dim3 grid(BATCH / (128 * 2), BLOCKS);   // (16, 64) = 1024 blocks
    for (int m = 0; m < DEPTH; m++) {
        const float* bia = biases + (size_t)m * 512;
        const int*   ix  = indices + (size_t)m * 1024;
        if (m == 0)
            module_kernel<1><<<grid, 128>>>(bia, ix, m, input, scales, nullptr);
        else if (m < DEPTH - 1)
            module_kernel<0><<<grid, 128>>>(bia, ix, m, nullptr, nullptr, nullptr);
        else
            module_kernel<2><<<grid, 128>>>(bia, ix, m, nullptr, nullptr, out);
    }
}